// round 10
// baseline (speedup 1.0000x reference)
#include <cuda_runtime.h>
#include <cuda_bf16.h>
#include <mma.h>
#include <cstdint>
#include <cstddef>

using namespace nvcuda;

// ---------------- problem constants ----------------
#define C_DIM 512
#define HW    4096
#define BATCH 2
#define NGRP  32
#define CPG   16

// ---------------- scratch (device globals; no allocs allowed) ----------------
__device__ __align__(16) __nv_bfloat16 g_hnT [(size_t)BATCH * HW * C_DIM];   // [b,hw,c]
__device__ __align__(16) __nv_bfloat16 g_W   [4 * C_DIM * C_DIM];
__device__ __align__(16) __nv_bfloat16 g_qT  [(size_t)BATCH * HW * C_DIM];   // [b,hw,c]
__device__ __align__(16) __nv_bfloat16 g_kT  [(size_t)BATCH * HW * C_DIM];   // [b,hw,c]
__device__ __align__(16) __nv_bfloat16 g_v   [(size_t)BATCH * C_DIM * HW];   // [b,c,hw]
__device__ __align__(16) float         g_scores[(size_t)BATCH * HW * HW];
__device__ __align__(16) __nv_bfloat16 g_attn  [(size_t)BATCH * HW * HW];
__device__ __align__(16) __nv_bfloat16 g_outA  [(size_t)BATCH * HW * C_DIM]; // [b,hw,c]

// ---------------- GroupNorm -> hnT [b,hw,c] directly ----------------
__global__ void gn_kernel(const float* __restrict__ x,
                          const float* __restrict__ gamma,
                          const float* __restrict__ beta,
                          __nv_bfloat16* __restrict__ hnT) {
    int b = blockIdx.x >> 5, g = blockIdx.x & 31;
    size_t base = ((size_t)b * C_DIM + g * CPG) * HW;
    const float4* xp = (const float4*)(x + base);
    int tid = threadIdx.x;

    float s = 0.f, s2 = 0.f;
    for (int v = tid; v < 16384; v += 256) {
        float4 t = xp[v];
        s  += t.x + t.y + t.z + t.w;
        s2 += t.x*t.x + t.y*t.y + t.z*t.z + t.w*t.w;
    }
    __shared__ float r1[256], r2[256];
    r1[tid] = s; r2[tid] = s2; __syncthreads();
    for (int st = 128; st > 0; st >>= 1) {
        if (tid < st) { r1[tid] += r1[tid+st]; r2[tid] += r2[tid+st]; }
        __syncthreads();
    }
    float mean = r1[0] * (1.0f/65536.0f);
    float var  = r2[0] * (1.0f/65536.0f) - mean*mean;
    float inv  = rsqrtf(var + 1e-6f);

    float ga[CPG], be[CPG];
    #pragma unroll
    for (int c = 0; c < CPG; ++c) {
        int gc = g * CPG + c;
        ga[c] = gamma[gc] * inv;
        be[c] = beta[gc] - mean * ga[c];
    }

    // write hnT[b][p][g*16 .. g*16+15] : one 32B vector per hw position
    __nv_bfloat16* dst = hnT + (size_t)b * HW * C_DIM + g * CPG;
    const float* xb = x + base;
    for (int p = tid; p < HW; p += 256) {
        __align__(16) __nv_bfloat16 tmp[CPG];
        #pragma unroll
        for (int c = 0; c < CPG; ++c) {
            float val = xb[(size_t)c * HW + p];
            tmp[c] = __float2bfloat16(val * ga[c] + be[c]);
        }
        *(uint4*)(dst + (size_t)p * C_DIM)     = *(const uint4*)tmp;
        *(uint4*)(dst + (size_t)p * C_DIM + 8) = *(const uint4*)(tmp + 8);
    }
}

// ---------------- weight fp32 -> bf16 ----------------
__global__ void convw_kernel(const float* __restrict__ wq, const float* __restrict__ wk,
                             const float* __restrict__ wv, const float* __restrict__ wo,
                             __nv_bfloat16* __restrict__ W) {
    int i = blockIdx.x * blockDim.x + threadIdx.x;
    const float* src;
    int which = i >> 18, off = i & 262143;
    src = (which == 0) ? wq : (which == 1) ? wk : (which == 2) ? wv : wo;
    W[i] = __float2bfloat16(src[off]);
}

// ---------------- row softmax: fp32 scores -> bf16 attn ----------------
__global__ void softmax_kernel(const float* __restrict__ scores,
                               __nv_bfloat16* __restrict__ attn) {
    const int n = HW;
    size_t row = blockIdx.x;
    const float4* src = (const float4*)(scores + row * n);
    __shared__ float buf[HW];
    __shared__ float red[256];
    int tid = threadIdx.x;

    float m = -1e30f;
    for (int v = tid; v < n/4; v += 256) {
        float4 t = src[v];
        ((float4*)buf)[v] = t;
        m = fmaxf(m, fmaxf(fmaxf(t.x, t.y), fmaxf(t.z, t.w)));
    }
    red[tid] = m; __syncthreads();
    for (int st = 128; st > 0; st >>= 1) {
        if (tid < st) red[tid] = fmaxf(red[tid], red[tid+st]);
        __syncthreads();
    }
    m = red[0];
    __syncthreads();

    float s = 0.f;
    for (int i = tid; i < n; i += 256) {
        float e = __expf(buf[i] - m);
        buf[i] = e;
        s += e;
    }
    red[tid] = s; __syncthreads();
    for (int st = 128; st > 0; st >>= 1) {
        if (tid < st) red[tid] += red[tid+st];
        __syncthreads();
    }
    float inv = 1.0f / red[0];
    __nv_bfloat16* dst = attn + row * (size_t)n;
    for (int i = tid; i < n; i += 256) dst[i] = __float2bfloat16(buf[i] * inv);
}

// ---------------- cp.async helpers ----------------
__device__ __forceinline__ void cps16(uint32_t dst, const void* src) {
    asm volatile("cp.async.cg.shared.global [%0], [%1], 16;" :: "r"(dst), "l"(src));
}
__device__ __forceinline__ void cp_commit() {
    asm volatile("cp.async.commit_group;" ::: "memory");
}

// ================ bf16 wmma GEMM, all-BCOL, BK=64, 3-stage cp.async ========
// C[m,n] = (sum_k A[m,k] * B[n,k] + bias) * scale (+ resid)
// A: [M,K] row-major, B: [N,K] row-major.  M,N % 128 == 0, K % 64 == 0.
// OUTF32: 0 = bf16 out, 1 = fp32 out. BIASMODE: 0 none, 1 per-M, 2 per-N.
#define BM 128
#define BN 128
#define BK 64
#define KPAD 72
#define TILE_EL (128 * KPAD)                 // 9216 bf16 per operand tile
#define STAGE_EL (2 * TILE_EL)               // 18432 bf16 = 36864 B
#define SMEM_BYTES (3 * STAGE_EL * 2)        // 110592 B

__device__ __forceinline__ void load_tile64(
    const __nv_bfloat16* __restrict__ Ab, const __nv_bfloat16* __restrict__ Bb,
    int kt, int lda, int ldb, int tid, uint32_t stage_u32)
{
    const __nv_bfloat16* Ag = Ab + kt * BK;
    const __nv_bfloat16* Bg = Bb + kt * BK;
    uint32_t sB_u32 = stage_u32 + TILE_EL * 2;
    #pragma unroll
    for (int v = 0; v < 4; ++v) {
        int idx = v * 256 + tid;              // 0..1023
        int r = idx >> 3, c = (idx & 7) << 3; // 8 x 16B per 128B row
        uint32_t so = (uint32_t)(r * KPAD + c) * 2;
        cps16(stage_u32 + so, Ag + (size_t)r * lda + c);
        cps16(sB_u32    + so, Bg + (size_t)r * ldb + c);
    }
}

template<int OUTF32, int BIASMODE, int RESID>
__global__ void __launch_bounds__(256)
gemm_kernel(const __nv_bfloat16* __restrict__ A, const __nv_bfloat16* __restrict__ B,
            void* __restrict__ C, const float* __restrict__ bias,
            const float* __restrict__ resid,
            int M, int N, int K, int lda, int ldb, int ldc,
            long long strideA, long long strideB, long long strideC, long long strideR,
            float scale)
{
    extern __shared__ __align__(16) char dsmem[];
    __nv_bfloat16* sbase = (__nv_bfloat16*)dsmem;
    float* sC = (float*)dsmem;                    // epilogue reuse: 64 x 132 fp32

    int tid  = threadIdx.x;
    int warp = tid >> 5;
    int wm = warp >> 2, wn = warp & 3;            // 2 x 4 warp grid, 64x32 warp tile
    int m0 = blockIdx.y * BM, n0 = blockIdx.x * BN;
    int bz = blockIdx.z;

    const __nv_bfloat16* Ab = A + (size_t)bz * strideA + (size_t)m0 * lda;
    const __nv_bfloat16* Bb = B + (size_t)bz * strideB + (size_t)n0 * ldb;

    uint32_t smem_u32 = (uint32_t)__cvta_generic_to_shared(sbase);

    wmma::fragment<wmma::accumulator, 16,16,16, float> acc[4][2];
    #pragma unroll
    for (int i = 0; i < 4; i++)
        #pragma unroll
        for (int j = 0; j < 2; j++) wmma::fill_fragment(acc[i][j], 0.0f);

    int nk = K / BK;

    // prologue: 2 stages in flight
    load_tile64(Ab, Bb, 0, lda, ldb, tid, smem_u32);
    cp_commit();
    if (nk > 1) {
        load_tile64(Ab, Bb, 1, lda, ldb, tid, smem_u32 + STAGE_EL * 2);
        cp_commit();
    }

    for (int kt = 0; kt < nk; ++kt) {
        if (kt + 1 < nk) asm volatile("cp.async.wait_group 1;" ::: "memory");
        else             asm volatile("cp.async.wait_group 0;" ::: "memory");
        __syncthreads();

        if (kt + 2 < nk) {
            load_tile64(Ab, Bb, kt + 2, lda, ldb, tid,
                        smem_u32 + (uint32_t)(((kt + 2) % 3) * STAGE_EL) * 2);
            cp_commit();
        }

        __nv_bfloat16* sA = sbase + (kt % 3) * STAGE_EL;
        __nv_bfloat16* sB = sA + TILE_EL;

        #pragma unroll
        for (int kk = 0; kk < 4; ++kk) {
            wmma::fragment<wmma::matrix_a, 16,16,16, __nv_bfloat16, wmma::row_major> af[4];
            #pragma unroll
            for (int i = 0; i < 4; i++)
                wmma::load_matrix_sync(af[i], &sA[(wm*64 + i*16) * KPAD + kk*16], KPAD);
            #pragma unroll
            for (int j = 0; j < 2; j++) {
                wmma::fragment<wmma::matrix_b, 16,16,16, __nv_bfloat16, wmma::col_major> bf;
                wmma::load_matrix_sync(bf, &sB[(wn*32 + j*16) * KPAD + kk*16], KPAD);
                #pragma unroll
                for (int i = 0; i < 4; i++) wmma::mma_sync(acc[i][j], af[i], bf, acc[i][j]);
            }
        }
    }

    // ---- epilogue: two 64-row chunks staged through smem ----
    #pragma unroll
    for (int chunk = 0; chunk < 2; ++chunk) {
        __syncthreads();
        if (wm == chunk) {
            #pragma unroll
            for (int i = 0; i < 4; i++)
                #pragma unroll
                for (int j = 0; j < 2; j++)
                    wmma::store_matrix_sync(&sC[(i*16) * 132 + wn*32 + j*16],
                                            acc[i][j], 132, wmma::mem_row_major);
        }
        __syncthreads();

        for (int idx = tid; idx < 64 * 128; idx += 256) {
            int r = idx >> 7, cn = idx & 127;
            int gm = m0 + chunk * 64 + r, gn = n0 + cn;
            float v = sC[r * 132 + cn];
            if (BIASMODE == 1) v += bias[gm];
            if (BIASMODE == 2) v += bias[gn];
            v *= scale;
            if (RESID) v += resid[(size_t)bz*strideR + (size_t)gm*N + gn];
            if (OUTF32)
                ((float*)C)[(size_t)bz*strideC + (size_t)gm*ldc + gn] = v;
            else
                ((__nv_bfloat16*)C)[(size_t)bz*strideC + (size_t)gm*ldc + gn] = __float2bfloat16(v);
        }
    }
}

// ---------------- launch ----------------
extern "C" void kernel_launch(void* const* d_in, const int* in_sizes, int n_in,
                              void* d_out, int out_size) {
    (void)in_sizes; (void)n_in; (void)out_size;
    const float* x     = (const float*)d_in[0];
    const float* gamma = (const float*)d_in[1];
    const float* beta  = (const float*)d_in[2];
    const float* wq    = (const float*)d_in[3];
    const float* bq    = (const float*)d_in[4];
    const float* wk    = (const float*)d_in[5];
    const float* bk    = (const float*)d_in[6];
    const float* wv    = (const float*)d_in[7];
    const float* bv    = (const float*)d_in[8];
    const float* wo    = (const float*)d_in[9];
    const float* bo    = (const float*)d_in[10];
    float* out = (float*)d_out;

    __nv_bfloat16 *hnT, *W, *qT, *kT, *v, *attn, *outA;
    float* scores;
    cudaGetSymbolAddress((void**)&hnT,    g_hnT);
    cudaGetSymbolAddress((void**)&W,      g_W);
    cudaGetSymbolAddress((void**)&qT,     g_qT);
    cudaGetSymbolAddress((void**)&kT,     g_kT);
    cudaGetSymbolAddress((void**)&v,      g_v);
    cudaGetSymbolAddress((void**)&scores, g_scores);
    cudaGetSymbolAddress((void**)&attn,   g_attn);
    cudaGetSymbolAddress((void**)&outA,   g_outA);

    cudaFuncSetAttribute((const void*)gemm_kernel<0,2,0>,
                         cudaFuncAttributeMaxDynamicSharedMemorySize, SMEM_BYTES);
    cudaFuncSetAttribute((const void*)gemm_kernel<0,1,0>,
                         cudaFuncAttributeMaxDynamicSharedMemorySize, SMEM_BYTES);
    cudaFuncSetAttribute((const void*)gemm_kernel<1,0,0>,
                         cudaFuncAttributeMaxDynamicSharedMemorySize, SMEM_BYTES);
    cudaFuncSetAttribute((const void*)gemm_kernel<0,0,0>,
                         cudaFuncAttributeMaxDynamicSharedMemorySize, SMEM_BYTES);
    cudaFuncSetAttribute((const void*)gemm_kernel<1,1,1>,
                         cudaFuncAttributeMaxDynamicSharedMemorySize, SMEM_BYTES);

    gn_kernel<<<BATCH * NGRP, 256>>>(x, gamma, beta, hnT);
    convw_kernel<<<4 * C_DIM * C_DIM / 256, 256>>>(wq, wk, wv, wo, W);

    const long long sT  = (long long)HW * C_DIM;   // 4096*512
    const long long sV  = (long long)C_DIM * HW;
    const long long sSC = (long long)HW * HW;
    const float qscale = 0.044194173824159216f;    // 512^-0.5

    // qT[p,o] = (hnT[p,:].Wq[o,:] + bq[o]) * qscale      [b,hw,c]
    gemm_kernel<0,2,0><<<dim3(C_DIM/BN, HW/BM, BATCH), 256, SMEM_BYTES>>>(
        hnT, W,            qT, bq, nullptr,
        HW, C_DIM, C_DIM, C_DIM, C_DIM, C_DIM, sT, 0, sT, 0, qscale);
    // kT[p,o] = hnT[p,:].Wk[o,:] + bk[o]                 [b,hw,c]
    gemm_kernel<0,2,0><<<dim3(C_DIM/BN, HW/BM, BATCH), 256, SMEM_BYTES>>>(
        hnT, W + 262144,   kT, bk, nullptr,
        HW, C_DIM, C_DIM, C_DIM, C_DIM, C_DIM, sT, 0, sT, 0, 1.0f);
    // v[o,p] = Wv[o,:].hnT[p,:] + bv[o]                  [b,c,hw]
    gemm_kernel<0,1,0><<<dim3(HW/BN, C_DIM/BM, BATCH), 256, SMEM_BYTES>>>(
        W + 2*262144, hnT, v,  bv, nullptr,
        C_DIM, HW, C_DIM, C_DIM, C_DIM, HW, 0, sT, sV, 0, 1.0f);

    // scores[i,j] = qT[i,:].kT[j,:]                      [b,hw,hw] fp32
    gemm_kernel<1,0,0><<<dim3(HW/BN, HW/BM, BATCH), 256, SMEM_BYTES>>>(
        qT, kT, scores, nullptr, nullptr,
        HW, HW, C_DIM, C_DIM, C_DIM, HW, sT, sT, sSC, 0, 1.0f);

    softmax_kernel<<<BATCH * HW, 256>>>(scores, attn);

    // outA[i,o] = attn[i,:].v[o,:]                       [b,hw,c]
    gemm_kernel<0,0,0><<<dim3(C_DIM/BN, HW/BM, BATCH), 256, SMEM_BYTES>>>(
        attn, v, outA, nullptr, nullptr,
        HW, C_DIM, HW, HW, HW, C_DIM, sSC, sV, sT, 0, 1.0f);

    // y[o,p] = x[o,p] + Wo[o,:].outA[p,:] + bo[o]        [b,c,hw] fp32
    gemm_kernel<1,1,1><<<dim3(HW/BN, C_DIM/BM, BATCH), 256, SMEM_BYTES>>>(
        W + 3*262144, outA, out, bo, x,
        C_DIM, HW, C_DIM, C_DIM, C_DIM, HW, 0, sT, sV, sV, 1.0f);
}

// round 15
// speedup vs baseline: 1.1893x; 1.1893x over previous
#include <cuda_runtime.h>
#include <cuda_bf16.h>
#include <mma.h>
#include <cstdint>
#include <cstddef>

using namespace nvcuda;

// ---------------- problem constants ----------------
#define C_DIM 512
#define HW    4096
#define BATCH 2
#define NGRP  32
#define CPG   16

// ---------------- scratch (device globals; no allocs allowed) ----------------
__device__ __align__(16) __nv_bfloat16 g_hnT [(size_t)BATCH * HW * C_DIM];   // [b,hw,c]
__device__ __align__(16) __nv_bfloat16 g_W   [4 * C_DIM * C_DIM];
__device__ __align__(16) __nv_bfloat16 g_qT  [(size_t)BATCH * HW * C_DIM];   // [b,hw,c]
__device__ __align__(16) __nv_bfloat16 g_kT  [(size_t)BATCH * HW * C_DIM];   // [b,hw,c]
__device__ __align__(16) __nv_bfloat16 g_v   [(size_t)BATCH * C_DIM * HW];   // [b,c,hw]
__device__ __align__(16) float         g_scores[(size_t)BATCH * HW * HW];
__device__ __align__(16) __nv_bfloat16 g_attn  [(size_t)BATCH * HW * HW];
__device__ __align__(16) __nv_bfloat16 g_outA  [(size_t)BATCH * HW * C_DIM]; // [b,hw,c]

// ---------------- GroupNorm -> hnT [b,hw,c] directly ----------------
__global__ void gn_kernel(const float* __restrict__ x,
                          const float* __restrict__ gamma,
                          const float* __restrict__ beta,
                          __nv_bfloat16* __restrict__ hnT) {
    int b = blockIdx.x >> 5, g = blockIdx.x & 31;
    size_t base = ((size_t)b * C_DIM + g * CPG) * HW;
    const float4* xp = (const float4*)(x + base);
    int tid = threadIdx.x;

    float s = 0.f, s2 = 0.f;
    for (int v = tid; v < 16384; v += 256) {
        float4 t = xp[v];
        s  += t.x + t.y + t.z + t.w;
        s2 += t.x*t.x + t.y*t.y + t.z*t.z + t.w*t.w;
    }
    __shared__ float r1[256], r2[256];
    r1[tid] = s; r2[tid] = s2; __syncthreads();
    for (int st = 128; st > 0; st >>= 1) {
        if (tid < st) { r1[tid] += r1[tid+st]; r2[tid] += r2[tid+st]; }
        __syncthreads();
    }
    float mean = r1[0] * (1.0f/65536.0f);
    float var  = r2[0] * (1.0f/65536.0f) - mean*mean;
    float inv  = rsqrtf(var + 1e-6f);

    float ga[CPG], be[CPG];
    #pragma unroll
    for (int c = 0; c < CPG; ++c) {
        int gc = g * CPG + c;
        ga[c] = gamma[gc] * inv;
        be[c] = beta[gc] - mean * ga[c];
    }

    // write hnT[b][p][g*16 .. g*16+15] : one 32B vector per hw position
    __nv_bfloat16* dst = hnT + (size_t)b * HW * C_DIM + g * CPG;
    const float* xb = x + base;
    for (int p = tid; p < HW; p += 256) {
        __align__(16) __nv_bfloat16 tmp[CPG];
        #pragma unroll
        for (int c = 0; c < CPG; ++c) {
            float val = xb[(size_t)c * HW + p];
            tmp[c] = __float2bfloat16(val * ga[c] + be[c]);
        }
        *(uint4*)(dst + (size_t)p * C_DIM)     = *(const uint4*)tmp;
        *(uint4*)(dst + (size_t)p * C_DIM + 8) = *(const uint4*)(tmp + 8);
    }
}

// ---------------- weight fp32 -> bf16 ----------------
__global__ void convw_kernel(const float* __restrict__ wq, const float* __restrict__ wk,
                             const float* __restrict__ wv, const float* __restrict__ wo,
                             __nv_bfloat16* __restrict__ W) {
    int i = blockIdx.x * blockDim.x + threadIdx.x;
    const float* src;
    int which = i >> 18, off = i & 262143;
    src = (which == 0) ? wq : (which == 1) ? wk : (which == 2) ? wv : wo;
    W[i] = __float2bfloat16(src[off]);
}

// ---------------- row softmax: fp32 scores -> bf16 attn ----------------
__global__ void softmax_kernel(const float* __restrict__ scores,
                               __nv_bfloat16* __restrict__ attn) {
    const int n = HW;
    size_t row = blockIdx.x;
    const float4* src = (const float4*)(scores + row * n);
    __shared__ float buf[HW];
    __shared__ float red[256];
    int tid = threadIdx.x;

    float m = -1e30f;
    for (int v = tid; v < n/4; v += 256) {
        float4 t = src[v];
        ((float4*)buf)[v] = t;
        m = fmaxf(m, fmaxf(fmaxf(t.x, t.y), fmaxf(t.z, t.w)));
    }
    red[tid] = m; __syncthreads();
    for (int st = 128; st > 0; st >>= 1) {
        if (tid < st) red[tid] = fmaxf(red[tid], red[tid+st]);
        __syncthreads();
    }
    m = red[0];
    __syncthreads();

    float s = 0.f;
    for (int i = tid; i < n; i += 256) {
        float e = __expf(buf[i] - m);
        buf[i] = e;
        s += e;
    }
    red[tid] = s; __syncthreads();
    for (int st = 128; st > 0; st >>= 1) {
        if (tid < st) red[tid] += red[tid+st];
        __syncthreads();
    }
    float inv = 1.0f / red[0];
    __nv_bfloat16* dst = attn + row * (size_t)n;
    for (int i = tid; i < n; i += 256) dst[i] = __float2bfloat16(buf[i] * inv);
}

// ---------------- cp.async helpers ----------------
__device__ __forceinline__ void cps16(uint32_t dst, const void* src) {
    asm volatile("cp.async.cg.shared.global [%0], [%1], 16;" :: "r"(dst), "l"(src));
}
__device__ __forceinline__ void cp_commit() {
    asm volatile("cp.async.commit_group;" ::: "memory");
}

// ================ bf16 wmma GEMM, all-BCOL, BK=64, 3-stage cp.async ========
// C[m,n] = (sum_k A[m,k] * B[n,k] + bias) * scale (+ resid)
// A: [M,K] row-major, B: [N,K] row-major.  M,N % 128 == 0, K % 64 == 0.
// OUTF32: 0 = bf16 out, 1 = fp32 out. BIASMODE: 0 none, 1 per-M, 2 per-N.
#define BM 128
#define BN 128
#define BK 64
#define KPAD 72
#define TILE_EL (128 * KPAD)                 // 9216 bf16 per operand tile
#define STAGE_EL (2 * TILE_EL)               // 18432 bf16 = 36864 B
#define SMEM_BYTES (3 * STAGE_EL * 2)        // 110592 B  (x2 CTAs = 221184 <= 228KB)

__device__ __forceinline__ void load_tile64(
    const __nv_bfloat16* __restrict__ Ab, const __nv_bfloat16* __restrict__ Bb,
    int kt, int lda, int ldb, int tid, uint32_t stage_u32)
{
    const __nv_bfloat16* Ag = Ab + kt * BK;
    const __nv_bfloat16* Bg = Bb + kt * BK;
    uint32_t sB_u32 = stage_u32 + TILE_EL * 2;
    #pragma unroll
    for (int v = 0; v < 4; ++v) {
        int idx = v * 256 + tid;              // 0..1023
        int r = idx >> 3, c = (idx & 7) << 3; // 8 x 16B per 128B row
        uint32_t so = (uint32_t)(r * KPAD + c) * 2;
        cps16(stage_u32 + so, Ag + (size_t)r * lda + c);
        cps16(sB_u32    + so, Bg + (size_t)r * ldb + c);
    }
}

template<int OUTF32, int BIASMODE, int RESID>
__global__ void __launch_bounds__(256, 2)     // force 2 CTAs/SM (<=128 regs/thread)
gemm_kernel(const __nv_bfloat16* __restrict__ A, const __nv_bfloat16* __restrict__ B,
            void* __restrict__ C, const float* __restrict__ bias,
            const float* __restrict__ resid,
            int M, int N, int K, int lda, int ldb, int ldc,
            long long strideA, long long strideB, long long strideC, long long strideR,
            float scale)
{
    extern __shared__ __align__(16) char dsmem[];
    __nv_bfloat16* sbase = (__nv_bfloat16*)dsmem;
    float* sC = (float*)dsmem;                    // epilogue reuse: 64 x 132 fp32

    int tid  = threadIdx.x;
    int warp = tid >> 5;
    int wm = warp >> 2, wn = warp & 3;            // 2 x 4 warp grid, 64x32 warp tile
    int m0 = blockIdx.y * BM, n0 = blockIdx.x * BN;
    int bz = blockIdx.z;

    const __nv_bfloat16* Ab = A + (size_t)bz * strideA + (size_t)m0 * lda;
    const __nv_bfloat16* Bb = B + (size_t)bz * strideB + (size_t)n0 * ldb;

    uint32_t smem_u32 = (uint32_t)__cvta_generic_to_shared(sbase);

    wmma::fragment<wmma::accumulator, 16,16,16, float> acc[4][2];
    #pragma unroll
    for (int i = 0; i < 4; i++)
        #pragma unroll
        for (int j = 0; j < 2; j++) wmma::fill_fragment(acc[i][j], 0.0f);

    int nk = K / BK;

    // prologue: 2 stages in flight
    load_tile64(Ab, Bb, 0, lda, ldb, tid, smem_u32);
    cp_commit();
    if (nk > 1) {
        load_tile64(Ab, Bb, 1, lda, ldb, tid, smem_u32 + STAGE_EL * 2);
        cp_commit();
    }

    for (int kt = 0; kt < nk; ++kt) {
        if (kt + 1 < nk) asm volatile("cp.async.wait_group 1;" ::: "memory");
        else             asm volatile("cp.async.wait_group 0;" ::: "memory");
        __syncthreads();

        if (kt + 2 < nk) {
            load_tile64(Ab, Bb, kt + 2, lda, ldb, tid,
                        smem_u32 + (uint32_t)(((kt + 2) % 3) * STAGE_EL) * 2);
            cp_commit();
        }

        __nv_bfloat16* sA = sbase + (kt % 3) * STAGE_EL;
        __nv_bfloat16* sB = sA + TILE_EL;

        #pragma unroll
        for (int kk = 0; kk < 4; ++kk) {
            wmma::fragment<wmma::matrix_a, 16,16,16, __nv_bfloat16, wmma::row_major> af[4];
            #pragma unroll
            for (int i = 0; i < 4; i++)
                wmma::load_matrix_sync(af[i], &sA[(wm*64 + i*16) * KPAD + kk*16], KPAD);
            #pragma unroll
            for (int j = 0; j < 2; j++) {
                wmma::fragment<wmma::matrix_b, 16,16,16, __nv_bfloat16, wmma::col_major> bf;
                wmma::load_matrix_sync(bf, &sB[(wn*32 + j*16) * KPAD + kk*16], KPAD);
                #pragma unroll
                for (int i = 0; i < 4; i++) wmma::mma_sync(acc[i][j], af[i], bf, acc[i][j]);
            }
        }
    }

    // ---- epilogue: two 64-row chunks staged through smem ----
    #pragma unroll
    for (int chunk = 0; chunk < 2; ++chunk) {
        __syncthreads();
        if (wm == chunk) {
            #pragma unroll
            for (int i = 0; i < 4; i++)
                #pragma unroll
                for (int j = 0; j < 2; j++)
                    wmma::store_matrix_sync(&sC[(i*16) * 132 + wn*32 + j*16],
                                            acc[i][j], 132, wmma::mem_row_major);
        }
        __syncthreads();

        for (int idx = tid; idx < 64 * 128; idx += 256) {
            int r = idx >> 7, cn = idx & 127;
            int gm = m0 + chunk * 64 + r, gn = n0 + cn;
            float v = sC[r * 132 + cn];
            if (BIASMODE == 1) v += bias[gm];
            if (BIASMODE == 2) v += bias[gn];
            v *= scale;
            if (RESID) v += resid[(size_t)bz*strideR + (size_t)gm*N + gn];
            if (OUTF32)
                ((float*)C)[(size_t)bz*strideC + (size_t)gm*ldc + gn] = v;
            else
                ((__nv_bfloat16*)C)[(size_t)bz*strideC + (size_t)gm*ldc + gn] = __float2bfloat16(v);
        }
    }
}

// ---------------- launch ----------------
extern "C" void kernel_launch(void* const* d_in, const int* in_sizes, int n_in,
                              void* d_out, int out_size) {
    (void)in_sizes; (void)n_in; (void)out_size;
    const float* x     = (const float*)d_in[0];
    const float* gamma = (const float*)d_in[1];
    const float* beta  = (const float*)d_in[2];
    const float* wq    = (const float*)d_in[3];
    const float* bq    = (const float*)d_in[4];
    const float* wk    = (const float*)d_in[5];
    const float* bk    = (const float*)d_in[6];
    const float* wv    = (const float*)d_in[7];
    const float* bv    = (const float*)d_in[8];
    const float* wo    = (const float*)d_in[9];
    const float* bo    = (const float*)d_in[10];
    float* out = (float*)d_out;

    __nv_bfloat16 *hnT, *W, *qT, *kT, *v, *attn, *outA;
    float* scores;
    cudaGetSymbolAddress((void**)&hnT,    g_hnT);
    cudaGetSymbolAddress((void**)&W,      g_W);
    cudaGetSymbolAddress((void**)&qT,     g_qT);
    cudaGetSymbolAddress((void**)&kT,     g_kT);
    cudaGetSymbolAddress((void**)&v,      g_v);
    cudaGetSymbolAddress((void**)&scores, g_scores);
    cudaGetSymbolAddress((void**)&attn,   g_attn);
    cudaGetSymbolAddress((void**)&outA,   g_outA);

    cudaFuncSetAttribute((const void*)gemm_kernel<0,2,0>,
                         cudaFuncAttributeMaxDynamicSharedMemorySize, SMEM_BYTES);
    cudaFuncSetAttribute((const void*)gemm_kernel<0,1,0>,
                         cudaFuncAttributeMaxDynamicSharedMemorySize, SMEM_BYTES);
    cudaFuncSetAttribute((const void*)gemm_kernel<1,0,0>,
                         cudaFuncAttributeMaxDynamicSharedMemorySize, SMEM_BYTES);
    cudaFuncSetAttribute((const void*)gemm_kernel<0,0,0>,
                         cudaFuncAttributeMaxDynamicSharedMemorySize, SMEM_BYTES);
    cudaFuncSetAttribute((const void*)gemm_kernel<1,1,1>,
                         cudaFuncAttributeMaxDynamicSharedMemorySize, SMEM_BYTES);

    gn_kernel<<<BATCH * NGRP, 256>>>(x, gamma, beta, hnT);
    convw_kernel<<<4 * C_DIM * C_DIM / 256, 256>>>(wq, wk, wv, wo, W);

    const long long sT  = (long long)HW * C_DIM;   // 4096*512
    const long long sV  = (long long)C_DIM * HW;
    const long long sSC = (long long)HW * HW;
    const float qscale = 0.044194173824159216f;    // 512^-0.5

    // qT[p,o] = (hnT[p,:].Wq[o,:] + bq[o]) * qscale      [b,hw,c]
    gemm_kernel<0,2,0><<<dim3(C_DIM/BN, HW/BM, BATCH), 256, SMEM_BYTES>>>(
        hnT, W,            qT, bq, nullptr,
        HW, C_DIM, C_DIM, C_DIM, C_DIM, C_DIM, sT, 0, sT, 0, qscale);
    // kT[p,o] = hnT[p,:].Wk[o,:] + bk[o]                 [b,hw,c]
    gemm_kernel<0,2,0><<<dim3(C_DIM/BN, HW/BM, BATCH), 256, SMEM_BYTES>>>(
        hnT, W + 262144,   kT, bk, nullptr,
        HW, C_DIM, C_DIM, C_DIM, C_DIM, C_DIM, sT, 0, sT, 0, 1.0f);
    // v[o,p] = Wv[o,:].hnT[p,:] + bv[o]                  [b,c,hw]
    gemm_kernel<0,1,0><<<dim3(HW/BN, C_DIM/BM, BATCH), 256, SMEM_BYTES>>>(
        W + 2*262144, hnT, v,  bv, nullptr,
        C_DIM, HW, C_DIM, C_DIM, C_DIM, HW, 0, sT, sV, 0, 1.0f);

    // scores[i,j] = qT[i,:].kT[j,:]                      [b,hw,hw] fp32
    gemm_kernel<1,0,0><<<dim3(HW/BN, HW/BM, BATCH), 256, SMEM_BYTES>>>(
        qT, kT, scores, nullptr, nullptr,
        HW, HW, C_DIM, C_DIM, C_DIM, HW, sT, sT, sSC, 0, 1.0f);

    softmax_kernel<<<BATCH * HW, 256>>>(scores, attn);

    // outA[i,o] = attn[i,:].v[o,:]                       [b,hw,c]
    gemm_kernel<0,0,0><<<dim3(C_DIM/BN, HW/BM, BATCH), 256, SMEM_BYTES>>>(
        attn, v, outA, nullptr, nullptr,
        HW, C_DIM, HW, HW, HW, C_DIM, sSC, sV, sT, 0, 1.0f);

    // y[o,p] = x[o,p] + Wo[o,:].outA[p,:] + bo[o]        [b,c,hw] fp32
    gemm_kernel<1,1,1><<<dim3(HW/BN, C_DIM/BM, BATCH), 256, SMEM_BYTES>>>(
        W + 3*262144, outA, out, bo, x,
        C_DIM, HW, C_DIM, C_DIM, C_DIM, HW, 0, sT, sV, sV, 1.0f);
}

// round 17
// speedup vs baseline: 1.4012x; 1.1781x over previous
#include <cuda_runtime.h>
#include <cuda_bf16.h>
#include <cstdint>
#include <cstddef>

// ---------------- problem constants ----------------
#define C_DIM 512
#define HW    4096
#define BATCH 2
#define NGRP  32
#define CPG   16

// ---------------- scratch (device globals; no allocs allowed) ----------------
__device__ __align__(16) __nv_bfloat16 g_hnT [(size_t)BATCH * HW * C_DIM];   // [b,hw,c]
__device__ __align__(16) __nv_bfloat16 g_W   [4 * C_DIM * C_DIM];
__device__ __align__(16) __nv_bfloat16 g_qT  [(size_t)BATCH * HW * C_DIM];   // [b,hw,c]
__device__ __align__(16) __nv_bfloat16 g_kT  [(size_t)BATCH * HW * C_DIM];   // [b,hw,c]
__device__ __align__(16) __nv_bfloat16 g_v   [(size_t)BATCH * C_DIM * HW];   // [b,c,hw]
__device__ __align__(16) float         g_scores[(size_t)BATCH * HW * HW];
__device__ __align__(16) __nv_bfloat16 g_attn  [(size_t)BATCH * HW * HW];
__device__ __align__(16) __nv_bfloat16 g_outA  [(size_t)BATCH * HW * C_DIM]; // [b,hw,c]

// ---------------- GroupNorm -> hnT [b,hw,c] directly ----------------
__global__ void gn_kernel(const float* __restrict__ x,
                          const float* __restrict__ gamma,
                          const float* __restrict__ beta,
                          __nv_bfloat16* __restrict__ hnT) {
    int b = blockIdx.x >> 5, g = blockIdx.x & 31;
    size_t base = ((size_t)b * C_DIM + g * CPG) * HW;
    const float4* xp = (const float4*)(x + base);
    int tid = threadIdx.x;

    float s = 0.f, s2 = 0.f;
    for (int v = tid; v < 16384; v += 256) {
        float4 t = xp[v];
        s  += t.x + t.y + t.z + t.w;
        s2 += t.x*t.x + t.y*t.y + t.z*t.z + t.w*t.w;
    }
    __shared__ float r1[256], r2[256];
    r1[tid] = s; r2[tid] = s2; __syncthreads();
    for (int st = 128; st > 0; st >>= 1) {
        if (tid < st) { r1[tid] += r1[tid+st]; r2[tid] += r2[tid+st]; }
        __syncthreads();
    }
    float mean = r1[0] * (1.0f/65536.0f);
    float var  = r2[0] * (1.0f/65536.0f) - mean*mean;
    float inv  = rsqrtf(var + 1e-6f);

    float ga[CPG], be[CPG];
    #pragma unroll
    for (int c = 0; c < CPG; ++c) {
        int gc = g * CPG + c;
        ga[c] = gamma[gc] * inv;
        be[c] = beta[gc] - mean * ga[c];
    }

    __nv_bfloat16* dst = hnT + (size_t)b * HW * C_DIM + g * CPG;
    const float* xb = x + base;
    for (int p = tid; p < HW; p += 256) {
        __align__(16) __nv_bfloat16 tmp[CPG];
        #pragma unroll
        for (int c = 0; c < CPG; ++c) {
            float val = xb[(size_t)c * HW + p];
            tmp[c] = __float2bfloat16(val * ga[c] + be[c]);
        }
        *(uint4*)(dst + (size_t)p * C_DIM)     = *(const uint4*)tmp;
        *(uint4*)(dst + (size_t)p * C_DIM + 8) = *(const uint4*)(tmp + 8);
    }
}

// ---------------- weight fp32 -> bf16 ----------------
__global__ void convw_kernel(const float* __restrict__ wq, const float* __restrict__ wk,
                             const float* __restrict__ wv, const float* __restrict__ wo,
                             __nv_bfloat16* __restrict__ W) {
    int i = blockIdx.x * blockDim.x + threadIdx.x;
    const float* src;
    int which = i >> 18, off = i & 262143;
    src = (which == 0) ? wq : (which == 1) ? wk : (which == 2) ? wv : wo;
    W[i] = __float2bfloat16(src[off]);
}

// ---------------- row softmax: fp32 scores -> bf16 attn ----------------
__global__ void softmax_kernel(const float* __restrict__ scores,
                               __nv_bfloat16* __restrict__ attn) {
    const int n = HW;
    size_t row = blockIdx.x;
    const float4* src = (const float4*)(scores + row * n);
    __shared__ float buf[HW];
    __shared__ float red[256];
    int tid = threadIdx.x;

    float m = -1e30f;
    for (int v = tid; v < n/4; v += 256) {
        float4 t = src[v];
        ((float4*)buf)[v] = t;
        m = fmaxf(m, fmaxf(fmaxf(t.x, t.y), fmaxf(t.z, t.w)));
    }
    red[tid] = m; __syncthreads();
    for (int st = 128; st > 0; st >>= 1) {
        if (tid < st) red[tid] = fmaxf(red[tid], red[tid+st]);
        __syncthreads();
    }
    m = red[0];
    __syncthreads();

    float s = 0.f;
    for (int i = tid; i < n; i += 256) {
        float e = __expf(buf[i] - m);
        buf[i] = e;
        s += e;
    }
    red[tid] = s; __syncthreads();
    for (int st = 128; st > 0; st >>= 1) {
        if (tid < st) red[tid] += red[tid+st];
        __syncthreads();
    }
    float inv = 1.0f / red[0];
    __nv_bfloat16* dst = attn + row * (size_t)n;
    for (int i = tid; i < n; i += 256) dst[i] = __float2bfloat16(buf[i] * inv);
}

// ---------------- asm helpers ----------------
__device__ __forceinline__ void cps16(uint32_t dst, const void* src) {
    asm volatile("cp.async.cg.shared.global [%0], [%1], 16;" :: "r"(dst), "l"(src));
}
__device__ __forceinline__ void cp_commit() {
    asm volatile("cp.async.commit_group;" ::: "memory");
}
__device__ __forceinline__ void ldsm4(uint32_t& r0, uint32_t& r1, uint32_t& r2, uint32_t& r3,
                                      uint32_t addr) {
    asm volatile("ldmatrix.sync.aligned.m8n8.x4.shared.b16 {%0,%1,%2,%3}, [%4];"
                 : "=r"(r0), "=r"(r1), "=r"(r2), "=r"(r3) : "r"(addr));
}
__device__ __forceinline__ void mma16816(float* c, const uint32_t* a, const uint32_t* b) {
    asm volatile("mma.sync.aligned.m16n8k16.row.col.f32.bf16.bf16.f32 "
                 "{%0,%1,%2,%3}, {%4,%5,%6,%7}, {%8,%9}, {%0,%1,%2,%3};"
                 : "+f"(c[0]), "+f"(c[1]), "+f"(c[2]), "+f"(c[3])
                 : "r"(a[0]), "r"(a[1]), "r"(a[2]), "r"(a[3]), "r"(b[0]), "r"(b[1]));
}

// ========== bf16 mma.sync GEMM, all-BCOL, BK=64, 3-stage cp.async ==========
// C[m,n] = (sum_k A[m,k] * B[n,k] + bias) * scale (+ resid)
// A: [M,K] row-major, B: [N,K] row-major.  M,N % 128 == 0, K % 64 == 0.
// OUTF32: 0 = bf16 out, 1 = fp32 out. BIASMODE: 0 none, 1 per-M, 2 per-N.
#define BM 128
#define BN 128
#define BK 64
#define KPAD 72
#define TILE_EL (128 * KPAD)                 // 9216 bf16 per operand tile
#define STAGE_EL (2 * TILE_EL)               // 36864 B per stage
#define SMEM_BYTES (3 * STAGE_EL * 2)        // 110592 B (x2 CTAs = 221184 <= 228KB)

__device__ __forceinline__ void load_tile64(
    const __nv_bfloat16* __restrict__ Ab, const __nv_bfloat16* __restrict__ Bb,
    int kt, int lda, int ldb, int tid, uint32_t stage_u32)
{
    const __nv_bfloat16* Ag = Ab + kt * BK;
    const __nv_bfloat16* Bg = Bb + kt * BK;
    uint32_t sB_u32 = stage_u32 + TILE_EL * 2;
    #pragma unroll
    for (int v = 0; v < 4; ++v) {
        int idx = v * 256 + tid;              // 0..1023
        int r = idx >> 3, c = (idx & 7) << 3; // 8 x 16B per 128B row
        uint32_t so = (uint32_t)(r * KPAD + c) * 2;
        cps16(stage_u32 + so, Ag + (size_t)r * lda + c);
        cps16(sB_u32    + so, Bg + (size_t)r * ldb + c);
    }
}

template<int OUTF32, int BIASMODE, int RESID>
__global__ void __launch_bounds__(256, 2)     // 2 CTAs/SM (<=128 regs/thread)
gemm_kernel(const __nv_bfloat16* __restrict__ A, const __nv_bfloat16* __restrict__ B,
            void* __restrict__ C, const float* __restrict__ bias,
            const float* __restrict__ resid,
            int M, int N, int K, int lda, int ldb, int ldc,
            long long strideA, long long strideB, long long strideC, long long strideR,
            float scale)
{
    extern __shared__ __align__(16) char dsmem[];
    __nv_bfloat16* sbase = (__nv_bfloat16*)dsmem;
    float* sC = (float*)dsmem;                    // epilogue reuse: 64 x 132 fp32

    int tid  = threadIdx.x;
    int warp = tid >> 5;
    int lane = tid & 31;
    int wm = warp >> 2, wn = warp & 3;            // 2 x 4 warp grid, 64x32 warp tile
    int m0 = blockIdx.y * BM, n0 = blockIdx.x * BN;
    int bz = blockIdx.z;

    const __nv_bfloat16* Ab = A + (size_t)bz * strideA + (size_t)m0 * lda;
    const __nv_bfloat16* Bb = B + (size_t)bz * strideB + (size_t)n0 * ldb;

    uint32_t smem_u32 = (uint32_t)__cvta_generic_to_shared(sbase);

    // per-lane ldmatrix base offsets (element units *2 = bytes)
    // A: lanes 0-15 -> rows m0-15, lanes 16-31 -> same rows, k+8
    uint32_t aoff = (uint32_t)(((wm * 64 + (lane & 15)) * KPAD + (lane >> 4) * 8) * 2);
    // B: groups of 8 lanes -> (ntile pair half, khalf): g0:(n0-7,k0-7) g1:(n0-7,k8-15)
    //    g2:(n8-15,k0-7) g3:(n8-15,k8-15)
    int g = lane >> 3;
    uint32_t boff = (uint32_t)(((wn * 32 + (g >> 1) * 8 + (lane & 7)) * KPAD + (g & 1) * 8) * 2);

    float acc[4][4][4];
    #pragma unroll
    for (int i = 0; i < 4; i++)
        #pragma unroll
        for (int j = 0; j < 4; j++)
            #pragma unroll
            for (int r = 0; r < 4; r++) acc[i][j][r] = 0.0f;

    int nk = K / BK;

    // prologue: 2 stages in flight
    load_tile64(Ab, Bb, 0, lda, ldb, tid, smem_u32);
    cp_commit();
    load_tile64(Ab, Bb, 1, lda, ldb, tid, smem_u32 + STAGE_EL * 2);
    cp_commit();

    uint32_t afrag[2][4][4];   // [buf][mtile][reg]
    uint32_t bfrag[2][4][2];   // [buf][ntile][reg]

    for (int kt = 0; kt < nk; ++kt) {
        if (kt + 1 < nk) asm volatile("cp.async.wait_group 1;" ::: "memory");
        else             asm volatile("cp.async.wait_group 0;" ::: "memory");
        __syncthreads();

        if (kt + 2 < nk) {
            load_tile64(Ab, Bb, kt + 2, lda, ldb, tid,
                        smem_u32 + (uint32_t)(((kt + 2) % 3) * STAGE_EL) * 2);
            cp_commit();
        }

        uint32_t sA_u = smem_u32 + (uint32_t)((kt % 3) * STAGE_EL) * 2;
        uint32_t sB_u = sA_u + TILE_EL * 2;

        // load fragments for kk = 0 into buf 0
        #pragma unroll
        for (int i = 0; i < 4; i++)
            ldsm4(afrag[0][i][0], afrag[0][i][1], afrag[0][i][2], afrag[0][i][3],
                  sA_u + aoff + (uint32_t)((i * 16 * KPAD) * 2));
        #pragma unroll
        for (int jp = 0; jp < 2; jp++)
            ldsm4(bfrag[0][2*jp][0], bfrag[0][2*jp][1], bfrag[0][2*jp+1][0], bfrag[0][2*jp+1][1],
                  sB_u + boff + (uint32_t)((jp * 16 * KPAD) * 2));

        #pragma unroll
        for (int kk = 0; kk < 4; ++kk) {
            int cur = kk & 1, nxt = cur ^ 1;
            if (kk < 3) {
                uint32_t ka = (uint32_t)((kk + 1) * 16 * 2);
                #pragma unroll
                for (int i = 0; i < 4; i++)
                    ldsm4(afrag[nxt][i][0], afrag[nxt][i][1], afrag[nxt][i][2], afrag[nxt][i][3],
                          sA_u + aoff + (uint32_t)((i * 16 * KPAD) * 2) + ka);
                #pragma unroll
                for (int jp = 0; jp < 2; jp++)
                    ldsm4(bfrag[nxt][2*jp][0], bfrag[nxt][2*jp][1],
                          bfrag[nxt][2*jp+1][0], bfrag[nxt][2*jp+1][1],
                          sB_u + boff + (uint32_t)((jp * 16 * KPAD) * 2) + ka);
            }
            #pragma unroll
            for (int i = 0; i < 4; i++)
                #pragma unroll
                for (int j = 0; j < 4; j++)
                    mma16816(acc[i][j], afrag[cur][i], bfrag[cur][j]);
        }
    }

    // ---- epilogue: two 64-row chunks staged through smem ----
    int crow = lane >> 2, ccol = (lane & 3) * 2;
    #pragma unroll
    for (int chunk = 0; chunk < 2; ++chunk) {
        __syncthreads();
        if (wm == chunk) {
            #pragma unroll
            for (int i = 0; i < 4; i++)
                #pragma unroll
                for (int j = 0; j < 4; j++) {
                    float* p0 = &sC[(i*16 + crow) * 132 + wn*32 + j*8 + ccol];
                    p0[0]   = acc[i][j][0];
                    p0[1]   = acc[i][j][1];
                    float* p1 = p0 + 8 * 132;
                    p1[0]   = acc[i][j][2];
                    p1[1]   = acc[i][j][3];
                }
        }
        __syncthreads();

        for (int idx = tid; idx < 64 * 128; idx += 256) {
            int r = idx >> 7, cn = idx & 127;
            int gm = m0 + chunk * 64 + r, gn = n0 + cn;
            float v = sC[r * 132 + cn];
            if (BIASMODE == 1) v += bias[gm];
            if (BIASMODE == 2) v += bias[gn];
            v *= scale;
            if (RESID) v += resid[(size_t)bz*strideR + (size_t)gm*N + gn];
            if (OUTF32)
                ((float*)C)[(size_t)bz*strideC + (size_t)gm*ldc + gn] = v;
            else
                ((__nv_bfloat16*)C)[(size_t)bz*strideC + (size_t)gm*ldc + gn] = __float2bfloat16(v);
        }
    }
}

// ---------------- launch ----------------
extern "C" void kernel_launch(void* const* d_in, const int* in_sizes, int n_in,
                              void* d_out, int out_size) {
    (void)in_sizes; (void)n_in; (void)out_size;
    const float* x     = (const float*)d_in[0];
    const float* gamma = (const float*)d_in[1];
    const float* beta  = (const float*)d_in[2];
    const float* wq    = (const float*)d_in[3];
    const float* bq    = (const float*)d_in[4];
    const float* wk    = (const float*)d_in[5];
    const float* bk    = (const float*)d_in[6];
    const float* wv    = (const float*)d_in[7];
    const float* bv    = (const float*)d_in[8];
    const float* wo    = (const float*)d_in[9];
    const float* bo    = (const float*)d_in[10];
    float* out = (float*)d_out;

    __nv_bfloat16 *hnT, *W, *qT, *kT, *v, *attn, *outA;
    float* scores;
    cudaGetSymbolAddress((void**)&hnT,    g_hnT);
    cudaGetSymbolAddress((void**)&W,      g_W);
    cudaGetSymbolAddress((void**)&qT,     g_qT);
    cudaGetSymbolAddress((void**)&kT,     g_kT);
    cudaGetSymbolAddress((void**)&v,      g_v);
    cudaGetSymbolAddress((void**)&scores, g_scores);
    cudaGetSymbolAddress((void**)&attn,   g_attn);
    cudaGetSymbolAddress((void**)&outA,   g_outA);

    cudaFuncSetAttribute((const void*)gemm_kernel<0,2,0>,
                         cudaFuncAttributeMaxDynamicSharedMemorySize, SMEM_BYTES);
    cudaFuncSetAttribute((const void*)gemm_kernel<0,1,0>,
                         cudaFuncAttributeMaxDynamicSharedMemorySize, SMEM_BYTES);
    cudaFuncSetAttribute((const void*)gemm_kernel<1,0,0>,
                         cudaFuncAttributeMaxDynamicSharedMemorySize, SMEM_BYTES);
    cudaFuncSetAttribute((const void*)gemm_kernel<0,0,0>,
                         cudaFuncAttributeMaxDynamicSharedMemorySize, SMEM_BYTES);
    cudaFuncSetAttribute((const void*)gemm_kernel<1,1,1>,
                         cudaFuncAttributeMaxDynamicSharedMemorySize, SMEM_BYTES);

    gn_kernel<<<BATCH * NGRP, 256>>>(x, gamma, beta, hnT);
    convw_kernel<<<4 * C_DIM * C_DIM / 256, 256>>>(wq, wk, wv, wo, W);

    const long long sT  = (long long)HW * C_DIM;   // 4096*512
    const long long sV  = (long long)C_DIM * HW;
    const long long sSC = (long long)HW * HW;
    const float qscale = 0.044194173824159216f;    // 512^-0.5

    // qT[p,o] = (hnT[p,:].Wq[o,:] + bq[o]) * qscale      [b,hw,c]
    gemm_kernel<0,2,0><<<dim3(C_DIM/BN, HW/BM, BATCH), 256, SMEM_BYTES>>>(
        hnT, W,            qT, bq, nullptr,
        HW, C_DIM, C_DIM, C_DIM, C_DIM, C_DIM, sT, 0, sT, 0, qscale);
    // kT[p,o] = hnT[p,:].Wk[o,:] + bk[o]                 [b,hw,c]
    gemm_kernel<0,2,0><<<dim3(C_DIM/BN, HW/BM, BATCH), 256, SMEM_BYTES>>>(
        hnT, W + 262144,   kT, bk, nullptr,
        HW, C_DIM, C_DIM, C_DIM, C_DIM, C_DIM, sT, 0, sT, 0, 1.0f);
    // v[o,p] = Wv[o,:].hnT[p,:] + bv[o]                  [b,c,hw]
    gemm_kernel<0,1,0><<<dim3(HW/BN, C_DIM/BM, BATCH), 256, SMEM_BYTES>>>(
        W + 2*262144, hnT, v,  bv, nullptr,
        C_DIM, HW, C_DIM, C_DIM, C_DIM, HW, 0, sT, sV, 0, 1.0f);

    // scores[i,j] = qT[i,:].kT[j,:]                      [b,hw,hw] fp32
    gemm_kernel<1,0,0><<<dim3(HW/BN, HW/BM, BATCH), 256, SMEM_BYTES>>>(
        qT, kT, scores, nullptr, nullptr,
        HW, HW, C_DIM, C_DIM, C_DIM, HW, sT, sT, sSC, 0, 1.0f);

    softmax_kernel<<<BATCH * HW, 256>>>(scores, attn);

    // outA[i,o] = attn[i,:].v[o,:]                       [b,hw,c]
    gemm_kernel<0,0,0><<<dim3(C_DIM/BN, HW/BM, BATCH), 256, SMEM_BYTES>>>(
        attn, v, outA, nullptr, nullptr,
        HW, C_DIM, HW, HW, HW, C_DIM, sSC, sV, sT, 0, 1.0f);

    // y[o,p] = x[o,p] + Wo[o,:].outA[p,:] + bo[o]        [b,c,hw] fp32
    gemm_kernel<1,1,1><<<dim3(HW/BN, C_DIM/BM, BATCH), 256, SMEM_BYTES>>>(
        W + 3*262144, outA, out, bo, x,
        C_DIM, HW, C_DIM, C_DIM, C_DIM, HW, 0, sT, sV, sV, 1.0f);
}